// round 9
// baseline (speedup 1.0000x reference)
#include <cuda_runtime.h>
#include <math.h>
#include <stdint.h>

#define BATCH 32
#define TSTEPS 12
#define NN 512
#define HH 64
#define EE 10

// ---------------- device state ----------------
__device__ float g_A[NN * NN];
__device__ float g_Alo[NN * NN];
__device__ float g_A2s[NN * NN];
__device__ float g_Ad[BATCH * NN * NN];
__device__ float g_Adlo[BATCH * NN * NN];
__device__ float g_A2d[BATCH * NN * NN];
__device__ float g_h[BATCH * NN * HH];
__device__ float g_zh[BATCH * NN * HH];
__device__ float g_r[BATCH * NN * HH];
__device__ float g_y1[BATCH * NN * 2];
__device__ float g_y2[BATCH * NN * 2];
__device__ float g_Edyn[BATCH * NN * EE];
__device__ float g_go[BATCH * NN];
// gate/upd partial sums
__device__ float g_gP1[BATCH * NN * 128];
__device__ float g_gP2[BATCH * NN * 128];
__device__ float g_uP1[BATCH * NN * 64];
__device__ float g_uP2[BATCH * NN * 64];
// repacked weights (hi/lo tf32), [ws]: 0=enc 1=dec
__device__ float g_WgAh[2][160 * 128], g_WgAl[2][160 * 128];
__device__ float g_WgBh[2][96 * 128],  g_WgBl[2][96 * 128];
__device__ float g_WuAh[2][160 * 64],  g_WuAl[2][160 * 64];
__device__ float g_WuBh[2][96 * 64],   g_WuBl[2][96 * 64];

__device__ __forceinline__ uint32_t tf32cvt(float x) {
    uint32_t r;
    asm("cvt.rna.tf32.f32 %0, %1;" : "=r"(r) : "f"(x));
    return r;
}

__device__ __forceinline__ void mma_tf32(float* d, uint32_t a0, uint32_t a1, uint32_t a2,
                                         uint32_t a3, uint32_t b0, uint32_t b1) {
    asm volatile(
        "mma.sync.aligned.m16n8k8.row.col.f32.tf32.tf32.f32 "
        "{%0,%1,%2,%3},{%4,%5,%6,%7},{%8,%9},{%0,%1,%2,%3};"
        : "+f"(d[0]), "+f"(d[1]), "+f"(d[2]), "+f"(d[3])
        : "r"(a0), "r"(a1), "r"(a2), "r"(a3), "r"(b0), "r"(b1));
}

__device__ __forceinline__ void cp_async16(uint32_t smem, const void* gmem) {
    asm volatile("cp.async.cg.shared.global [%0], [%1], 16;" :: "r"(smem), "l"(gmem));
}
__device__ __forceinline__ void cp_commit() { asm volatile("cp.async.commit_group;"); }
__device__ __forceinline__ void cp_wait0() { asm volatile("cp.async.wait_group 0;"); }

// ---------------- init ----------------
__global__ void zero_state() {
    int i = blockIdx.x * 256 + threadIdx.x;
    if (i < BATCH * NN * HH) g_h[i] = 0.f;
    if (i < BATCH * NN) g_go[i] = 0.f;
}

// ---------------- weight repack: hi/lo tf32, zero-padded ----------------
__global__ void repack_w(const float* __restrict__ src, float* __restrict__ dh,
                         float* __restrict__ dl, int srcoff, int nrows, int nout, int kpad) {
    int i = blockIdx.x * 256 + threadIdx.x;
    if (i >= kpad * nout) return;
    int r = i / nout;
    float v = (r < nrows) ? src[(srcoff + r) * nout + (i - r * nout)] : 0.f;
    float h = __uint_as_float(tf32cvt(v));
    dh[i] = h;
    dl[i] = __uint_as_float(tf32cvt(v - h));
}

// ---------------- graph build (hi/lo) ----------------
template <bool DYN>
__global__ void graph_build(const float* __restrict__ emb) {
    __shared__ float Es[NN * EE];
    __shared__ float red[8];
    int blk = blockIdx.x;
    int b = DYN ? (blk >> 9) : 0;
    int row = blk & (NN - 1);
    const float* E = DYN ? (g_Edyn + b * NN * EE) : emb;
    int tid = threadIdx.x;
    for (int i = tid; i < NN * EE; i += 256) Es[i] = E[i];
    __syncthreads();
    float er[EE];
#pragma unroll
    for (int j = 0; j < EE; j++) er[j] = Es[row * EE + j];
    float v0 = 0.f, v1 = 0.f;
    int c0 = tid, c1 = tid + 256;
#pragma unroll
    for (int j = 0; j < EE; j++) {
        v0 += er[j] * Es[c0 * EE + j];
        v1 += er[j] * Es[c1 * EE + j];
    }
    v0 = fmaxf(v0, 0.f);
    v1 = fmaxf(v1, 0.f);
    float m = fmaxf(v0, v1);
#pragma unroll
    for (int o = 16; o; o >>= 1) m = fmaxf(m, __shfl_xor_sync(0xffffffffu, m, o));
    if ((tid & 31) == 0) red[tid >> 5] = m;
    __syncthreads();
    m = red[0];
#pragma unroll
    for (int i = 1; i < 8; i++) m = fmaxf(m, red[i]);
    float e0 = expf(v0 - m), e1 = expf(v1 - m);
    float s = e0 + e1;
#pragma unroll
    for (int o = 16; o; o >>= 1) s += __shfl_xor_sync(0xffffffffu, s, o);
    __syncthreads();
    if ((tid & 31) == 0) red[tid >> 5] = s;
    __syncthreads();
    float tot = 0.f;
#pragma unroll
    for (int i = 0; i < 8; i++) tot += red[i];
    float inv = 1.f / tot;
    size_t off = DYN ? ((size_t)b * NN * NN + (size_t)row * NN) : ((size_t)row * NN);
    float* hi = (DYN ? g_Ad : g_A) + off;
    float* lo = (DYN ? g_Adlo : g_Alo) + off;
    float a0 = e0 * inv, a1 = e1 * inv;
    float h0 = __uint_as_float(tf32cvt(a0));
    float h1 = __uint_as_float(tf32cvt(a1));
    hi[c0] = h0; hi[c1] = h1;
    lo[c0] = __uint_as_float(tf32cvt(a0 - h0));
    lo[c1] = __uint_as_float(tf32cvt(a1 - h1));
}

// ---------------- hypernetwork ----------------
__global__ void hyper_kernel(const float* __restrict__ ne,
                             const float* __restrict__ hW,
                             const float* __restrict__ hb) {
    __shared__ float Ws[HH * EE];
    int tid = threadIdx.x;
    for (int i = tid; i < HH * EE; i += 256) Ws[i] = hW[i];
    __syncthreads();
    int lr = tid >> 4, e = tid & 15;
    int row = blockIdx.x * 16 + lr;
    if (e < EE) {
        float acc = hb[e];
        const float* hp = g_h + row * HH;
#pragma unroll
        for (int j = 0; j < HH; j++) acc += hp[j] * Ws[j * EE + e];
        int n = row & (NN - 1);
        g_Edyn[row * EE + e] = ne[n * EE + e] + acc;
    }
}

// ---------------- gemm512 (A^2 passes) ----------------
#define AS 36
#define XS 72
template <int PASS, bool DYN>
__global__ void __launch_bounds__(128) gemm512(int asel, int bsel) {
    __shared__ float As[2][64 * AS];
    __shared__ float Bs[2][32 * XS];
    int i0 = blockIdx.x * 64;
    int j0 = blockIdx.y * 64;
    int bz = blockIdx.z;
    size_t boff = (size_t)bz * NN * NN;
    const float* base_hi = (DYN ? g_Ad : g_A) + boff;
    const float* base_lo = (DYN ? g_Adlo : g_Alo) + boff;
    const float* Ma = (asel ? base_lo : base_hi) + (size_t)i0 * NN;
    const float* Mb = (bsel ? base_lo : base_hi) + j0;
    float* Out = (DYN ? g_A2d : g_A2s) + boff;
    int tid = threadIdx.x;

#pragma unroll
    for (int q = 0; q < 4; q++) {
        int idx = tid + q * 128;
        int r = idx >> 3, c4 = idx & 7;
        cp_async16((uint32_t)__cvta_generic_to_shared(&As[0][r * AS + c4 * 4]),
                   &Ma[(size_t)r * NN + c4 * 4]);
    }
#pragma unroll
    for (int q = 0; q < 4; q++) {
        int idx = tid + q * 128;
        int k = idx >> 4, n4 = idx & 15;
        cp_async16((uint32_t)__cvta_generic_to_shared(&Bs[0][k * XS + n4 * 4]),
                   &Mb[(size_t)k * NN + n4 * 4]);
    }
    cp_commit();
    cp_wait0();
    __syncthreads();

    int lane = tid & 31, w = tid >> 5;
    int gid = lane >> 2, tq = lane & 3;
    int R = (w & 1) * 32;
    int CH = (w >> 1) * 32;
    float acc[2][4][4];
#pragma unroll
    for (int rr = 0; rr < 2; rr++)
#pragma unroll
        for (int j = 0; j < 4; j++)
#pragma unroll
            for (int c = 0; c < 4; c++) acc[rr][j][c] = 0.f;

    for (int it = 0; it < 16; it++) {
        int buf = it & 1, nxt = buf ^ 1;
        int k0n = (it + 1) * 32;
        if (it < 15) {
#pragma unroll
            for (int q = 0; q < 4; q++) {
                int idx = tid + q * 128;
                int r = idx >> 3, c4 = idx & 7;
                cp_async16((uint32_t)__cvta_generic_to_shared(&As[nxt][r * AS + c4 * 4]),
                           &Ma[(size_t)r * NN + k0n + c4 * 4]);
            }
#pragma unroll
            for (int q = 0; q < 4; q++) {
                int idx = tid + q * 128;
                int k = idx >> 4, n4 = idx & 15;
                cp_async16((uint32_t)__cvta_generic_to_shared(&Bs[nxt][k * XS + n4 * 4]),
                           &Mb[(size_t)(k0n + k) * NN + n4 * 4]);
            }
            cp_commit();
        }
        const float* Ac = As[buf];
        const float* Bc = Bs[buf];
#pragma unroll
        for (int ks = 0; ks < 4; ks++) {
            int kb = ks * 8;
            uint32_t b0[4], b1[4];
#pragma unroll
            for (int j = 0; j < 4; j++) {
                int nb = CH + j * 8;
                b0[j] = __float_as_uint(Bc[(kb + tq) * XS + nb + gid]);
                b1[j] = __float_as_uint(Bc[(kb + tq + 4) * XS + nb + gid]);
            }
#pragma unroll
            for (int rr = 0; rr < 2; rr++) {
                int Rr = R + rr * 16;
                uint32_t a0 = __float_as_uint(Ac[(Rr + gid) * AS + kb + tq]);
                uint32_t a1 = __float_as_uint(Ac[(Rr + gid + 8) * AS + kb + tq]);
                uint32_t a2 = __float_as_uint(Ac[(Rr + gid) * AS + kb + tq + 4]);
                uint32_t a3 = __float_as_uint(Ac[(Rr + gid + 8) * AS + kb + tq + 4]);
#pragma unroll
                for (int j = 0; j < 4; j++)
                    mma_tf32(acc[rr][j], a0, a1, a2, a3, b0[j], b1[j]);
            }
        }
        if (it < 15) cp_wait0();
        __syncthreads();
    }

#pragma unroll
    for (int rr = 0; rr < 2; rr++) {
#pragma unroll
        for (int j = 0; j < 4; j++) {
            int col = j0 + CH + j * 8 + 2 * tq;
            int row0 = i0 + R + rr * 16 + gid;
            int row1 = row0 + 8;
#pragma unroll
            for (int e = 0; e < 4; e++) {
                int row = (e < 2) ? row0 : row1;
                int cc = col + (e & 1);
                size_t o = (size_t)row * NN + cc;
                float v = acc[rr][j][e];
                if (PASS == 0) Out[o] = v;
                else if (PASS == 1) Out[o] += v;
                else Out[o] = __uint_as_float(tf32cvt(2.f * (Out[o] + v)));
            }
        }
    }
}

// ---------------- fused conv + weight-GEMM epilogue ----------------
// grid (16, BATCH), 128 threads, dynamic smem 78848 B.
// blocks 0-7: family A (graph A), 8-15: family B (2A^2).
// NOUT=128: phase gate (X = h, lead fold, writes g_gP1/g_gP2, y1/y2).
// NOUT=64 : phase upd  (X = zh, leads from gmem, writes g_uP1/g_uP2).
template <bool BA, int L, int LMODE, int NOUT>
__global__ void __launch_bounds__(128) conv_fused(int ws, const float* __restrict__ xsrc, int t) {
    extern __shared__ float smem[];
    constexpr bool PH0 = (NOUT == 128);
    int b = blockIdx.y;
    int rt = blockIdx.x;
    bool second = rt >= 8;
    int i0 = (second ? rt - 8 : rt) * 64;
    const float* Mbase;
    if (BA) Mbase = (second ? g_A2d : g_Ad) + (size_t)b * NN * NN;
    else    Mbase = second ? g_A2s : g_A;
    Mbase += (size_t)i0 * NN;
    const float* Xb = (PH0 ? g_h : g_zh) + b * NN * HH;
    int tid = threadIdx.x;
    float* As0 = smem;
    float* Xs0 = smem + 4608;
    float* xsl = smem + 18560;
    float* ysm = smem + 19584;

    if (PH0) {
        for (int i = tid; i < NN * L; i += 128) {
            int k = i / L, c = i - (i / L) * L;
            float v;
            if (LMODE == 0) v = xsrc[(b * TSTEPS + t) * NN + k];
            else v = (c == 0) ? g_go[b * NN + k] : xsrc[(b * TSTEPS + t) * NN + k];
            xsl[i] = v;
        }
    }

    float4 xr[4];
#pragma unroll
    for (int q = 0; q < 4; q++) {
        int idx = tid + q * 128;
        int r = idx >> 3, c4 = idx & 7;
        cp_async16((uint32_t)__cvta_generic_to_shared(&As0[r * AS + c4 * 4]),
                   &Mbase[(size_t)r * NN + c4 * 4]);
    }
    cp_commit();
#pragma unroll
    for (int q = 0; q < 4; q++) {
        int idx = tid + q * 128;
        int k = idx >> 4, n4 = idx & 15;
        xr[q] = *(const float4*)&Xb[k * HH + n4 * 4];
    }
#pragma unroll
    for (int q = 0; q < 4; q++) {
        int idx = tid + q * 128;
        int k = idx >> 4, n4 = idx & 15;
        float4 v = xr[q];
        v.x = __uint_as_float(tf32cvt(v.x));
        v.y = __uint_as_float(tf32cvt(v.y));
        v.z = __uint_as_float(tf32cvt(v.z));
        v.w = __uint_as_float(tf32cvt(v.w));
        *(float4*)&Xs0[k * XS + n4 * 4] = v;
    }
    cp_wait0();
    __syncthreads();

    int lane = tid & 31, w = tid >> 5;
    int gid = lane >> 2, tq = lane & 3;
    int R = (w & 1) * 32;
    int CH = (w >> 1) * 32;
    float acc[2][4][4];
#pragma unroll
    for (int rr = 0; rr < 2; rr++)
#pragma unroll
        for (int j = 0; j < 4; j++)
#pragma unroll
            for (int c = 0; c < 4; c++) acc[rr][j][c] = 0.f;

    int lrow = tid >> 1, lhalf = tid & 1;
    float lacc0 = 0.f, lacc1 = 0.f;

    for (int it = 0; it < 16; it++) {
        int buf = it & 1, nxt = buf ^ 1;
        int k0n = (it + 1) * 32;
        if (it < 15) {
#pragma unroll
            for (int q = 0; q < 4; q++) {
                int idx = tid + q * 128;
                int r = idx >> 3, c4 = idx & 7;
                cp_async16((uint32_t)__cvta_generic_to_shared(&As0[nxt * 2304 + r * AS + c4 * 4]),
                           &Mbase[(size_t)r * NN + k0n + c4 * 4]);
            }
            cp_commit();
#pragma unroll
            for (int q = 0; q < 4; q++) {
                int idx = tid + q * 128;
                int k = idx >> 4, n4 = idx & 15;
                xr[q] = *(const float4*)&Xb[(k0n + k) * HH + n4 * 4];
            }
        }
        const float* Ac = As0 + buf * 2304;
        const float* Xc = Xs0 + buf * 2304;
#pragma unroll
        for (int kss = 0; kss < 4; kss++) {
            int kb = kss * 8;
            uint32_t b0[4], b1[4];
#pragma unroll
            for (int j = 0; j < 4; j++) {
                int nb = CH + j * 8;
                b0[j] = __float_as_uint(Xc[(kb + tq) * XS + nb + gid]);
                b1[j] = __float_as_uint(Xc[(kb + tq + 4) * XS + nb + gid]);
            }
#pragma unroll
            for (int rr = 0; rr < 2; rr++) {
                int Rr = R + rr * 16;
                uint32_t a0 = __float_as_uint(Ac[(Rr + gid) * AS + kb + tq]);
                uint32_t a1 = __float_as_uint(Ac[(Rr + gid + 8) * AS + kb + tq]);
                uint32_t a2 = __float_as_uint(Ac[(Rr + gid) * AS + kb + tq + 4]);
                uint32_t a3 = __float_as_uint(Ac[(Rr + gid + 8) * AS + kb + tq + 4]);
#pragma unroll
                for (int j = 0; j < 4; j++)
                    mma_tf32(acc[rr][j], a0, a1, a2, a3, b0[j], b1[j]);
            }
        }
        if (PH0) {
            int k0 = it * 32;
#pragma unroll
            for (int j = 0; j < 16; j++) {
                int k = lhalf * 16 + j;
                float a = Ac[lrow * AS + k];
                lacc0 += a * xsl[(k0 + k) * L];
                if (L == 2) lacc1 += a * xsl[(k0 + k) * L + 1];
            }
        }
        if (it < 15) {
#pragma unroll
            for (int q = 0; q < 4; q++) {
                int idx = tid + q * 128;
                int k = idx >> 4, n4 = idx & 15;
                float4 v = xr[q];
                v.x = __uint_as_float(tf32cvt(v.x));
                v.y = __uint_as_float(tf32cvt(v.y));
                v.z = __uint_as_float(tf32cvt(v.z));
                v.w = __uint_as_float(tf32cvt(v.w));
                *(float4*)&Xs0[nxt * 2304 + k * XS + n4 * 4] = v;
            }
            cp_wait0();
        }
        __syncthreads();
    }

    // ================= epilogue =================
    const int CINv = L + 64;
    const int KP1 = second ? 97 : 161;
    const int KT = second ? 3 : 5;
    float* Xg = smem;
    float* Wsh = smem + 10304;
    float* Wsl = smem + 14432;

    if (PH0) {
        lacc0 += __shfl_xor_sync(0xffffffffu, lacc0, 1);
        if (L == 2) lacc1 += __shfl_xor_sync(0xffffffffu, lacc1, 1);
        if (lhalf == 0) {
            if (!second) {
                g_y1[(b * NN + i0 + lrow) * L] = lacc0;
                ysm[lrow * L] = lacc0;
                if (L == 2) { g_y1[(b * NN + i0 + lrow) * L + 1] = lacc1; ysm[lrow * L + 1] = lacc1; }
            } else {
                g_y2[(b * NN + i0 + lrow) * L] = 0.5f * lacc0;
                ysm[lrow * L] = lacc0;   // raw 2A^2 @ lead
                if (L == 2) { g_y2[(b * NN + i0 + lrow) * L + 1] = 0.5f * lacc1; ysm[lrow * L + 1] = lacc1; }
            }
        }
    }
    __syncthreads();

    // zero Xg
    for (int i = tid; i < 64 * 161; i += 128) Xg[i] = 0.f;
    __syncthreads();

    // fill lead/main/ylead columns (2 threads per row).
    // FIX (R8 bug): for the `second` family, the u2 scatter below owns columns
    // [L, L+64); fill must write ONLY the lead columns [0, L) to avoid the
    // unordered write-write hazard that corrupted famB's X in R8.
    {
        int r = lrow;
        const float* XbRow = Xb + (i0 + r) * HH;
        int cmax = second ? L : CINv;
        for (int c = lhalf; c < cmax; c += 2) {
            float v;
            if (c < L) {
                float x0;
                if (PH0) x0 = xsl[(i0 + r) * L + c];
                else {
                    int gk = i0 + r;
                    if (LMODE == 0) x0 = xsrc[(b * TSTEPS + t) * NN + gk];
                    else x0 = (c == 0) ? g_go[b * NN + gk] : xsrc[(b * TSTEPS + t) * NN + gk];
                }
                if (!second) v = x0;
                else {
                    float yv = PH0 ? ysm[r * L + c] : 2.f * g_y2[(b * NN + i0 + r) * L + c];
                    v = yv - x0;
                }
            } else {
                v = XbRow[c - L];
            }
            Xg[r * KP1 + c] = v;
        }
        if (!second) {
            for (int c = lhalf; c < L; c += 2) {
                float yv = PH0 ? ysm[r * L + c] : g_y1[(b * NN + i0 + r) * L + c];
                Xg[r * KP1 + CINv + c] = yv;
            }
        }
    }

    // scatter conv acc into u columns (disjoint from fill after the fix)
    {
        int ubase = second ? L : (CINv + L);
#pragma unroll
        for (int rr = 0; rr < 2; rr++) {
#pragma unroll
            for (int j = 0; j < 4; j++) {
                int colu = CH + j * 8 + 2 * tq;
                int r0w = R + rr * 16 + gid, r1w = r0w + 8;
                float s00 = acc[rr][j][0], s01 = acc[rr][j][1];
                float s10 = acc[rr][j][2], s11 = acc[rr][j][3];
                if (second) {
                    float2 m0 = *(const float2*)&Xb[(i0 + r0w) * HH + colu];
                    float2 m1 = *(const float2*)&Xb[(i0 + r1w) * HH + colu];
                    s00 -= m0.x; s01 -= m0.y; s10 -= m1.x; s11 -= m1.y;
                }
                Xg[r0w * KP1 + ubase + colu] = s00;
                Xg[r0w * KP1 + ubase + colu + 1] = s01;
                Xg[r1w * KP1 + ubase + colu] = s10;
                Xg[r1w * KP1 + ubase + colu + 1] = s11;
            }
        }
    }
    __syncthreads();

    // W-GEMM: acc2 += Xh@Wh + Xl@Wh + Xh@Wl
    const float* Wh;
    const float* Wl;
    if (NOUT == 128) {
        Wh = second ? g_WgBh[ws] : g_WgAh[ws];
        Wl = second ? g_WgBl[ws] : g_WgAl[ws];
    } else {
        Wh = second ? g_WuBh[ws] : g_WuAh[ws];
        Wl = second ? g_WuBl[ws] : g_WuAl[ws];
    }
    const int NOUTP = NOUT + 1;
    const int NJ = NOUT / 16;
    const int CH2 = (w >> 1) * (NOUT / 2);
    float acc2[2][8][4];
#pragma unroll
    for (int rr = 0; rr < 2; rr++)
#pragma unroll
        for (int j = 0; j < 8; j++)
#pragma unroll
            for (int c = 0; c < 4; c++) acc2[rr][j][c] = 0.f;

    for (int kt = 0; kt < KT; kt++) {
        for (int i = tid; i < 32 * NOUT; i += 128) {
            int rr2 = i / NOUT, cc2 = i - rr2 * NOUT;
            Wsh[rr2 * NOUTP + cc2] = Wh[(kt * 32 + rr2) * NOUT + cc2];
            Wsl[rr2 * NOUTP + cc2] = Wl[(kt * 32 + rr2) * NOUT + cc2];
        }
        __syncthreads();
#pragma unroll
        for (int ks2 = 0; ks2 < 4; ks2++) {
            int kb = ks2 * 8, kg = kt * 32 + kb;
            uint32_t ah[2][4], al[2][4];
#pragma unroll
            for (int rr = 0; rr < 2; rr++) {
                int r0w = R + rr * 16 + gid;
                float f0 = Xg[r0w * KP1 + kg + tq];
                float f1 = Xg[(r0w + 8) * KP1 + kg + tq];
                float f2 = Xg[r0w * KP1 + kg + tq + 4];
                float f3 = Xg[(r0w + 8) * KP1 + kg + tq + 4];
                ah[rr][0] = tf32cvt(f0); al[rr][0] = tf32cvt(f0 - __uint_as_float(ah[rr][0]));
                ah[rr][1] = tf32cvt(f1); al[rr][1] = tf32cvt(f1 - __uint_as_float(ah[rr][1]));
                ah[rr][2] = tf32cvt(f2); al[rr][2] = tf32cvt(f2 - __uint_as_float(ah[rr][2]));
                ah[rr][3] = tf32cvt(f3); al[rr][3] = tf32cvt(f3 - __uint_as_float(ah[rr][3]));
            }
#pragma unroll
            for (int j = 0; j < 8; j++) {
                if (j >= NJ) break;
                int nb = CH2 + j * 8;
                uint32_t bh0 = __float_as_uint(Wsh[(kb + tq) * NOUTP + nb + gid]);
                uint32_t bh1 = __float_as_uint(Wsh[(kb + tq + 4) * NOUTP + nb + gid]);
                uint32_t bl0 = __float_as_uint(Wsl[(kb + tq) * NOUTP + nb + gid]);
                uint32_t bl1 = __float_as_uint(Wsl[(kb + tq + 4) * NOUTP + nb + gid]);
#pragma unroll
                for (int rr = 0; rr < 2; rr++) {
                    mma_tf32(acc2[rr][j], ah[rr][0], ah[rr][1], ah[rr][2], ah[rr][3], bh0, bh1);
                    mma_tf32(acc2[rr][j], al[rr][0], al[rr][1], al[rr][2], al[rr][3], bh0, bh1);
                    mma_tf32(acc2[rr][j], ah[rr][0], ah[rr][1], ah[rr][2], ah[rr][3], bl0, bl1);
                }
            }
        }
        __syncthreads();
    }

    float* OP = second ? (NOUT == 128 ? g_gP2 : g_uP2) : (NOUT == 128 ? g_gP1 : g_uP1);
    OP += (size_t)b * NN * NOUT;
#pragma unroll
    for (int rr = 0; rr < 2; rr++) {
#pragma unroll
        for (int j = 0; j < 8; j++) {
            if (j >= NJ) break;
            int col = CH2 + j * 8 + 2 * tq;
            int r0w = i0 + R + rr * 16 + gid, r1w = r0w + 8;
            *(float2*)&OP[r0w * NOUT + col] = make_float2(acc2[rr][j][0], acc2[rr][j][1]);
            *(float2*)&OP[r1w * NOUT + col] = make_float2(acc2[rr][j][2], acc2[rr][j][3]);
        }
    }
}

// ---------------- finalize gate ----------------
__global__ void fin_gate(const float* __restrict__ bias) {
    int tid = threadIdx.x;
    int row = blockIdx.x * 4 + (tid >> 6);
    int j = tid & 63;
    float z = g_gP1[row * 128 + j] + g_gP2[row * 128 + j] + bias[j];
    float r = g_gP1[row * 128 + 64 + j] + g_gP2[row * 128 + 64 + j] + bias[64 + j];
    z = 1.f / (1.f + expf(-z));
    r = 1.f / (1.f + expf(-r));
    g_zh[row * HH + j] = z * g_h[row * HH + j];
    g_r[row * HH + j] = r;
}

// ---------------- finalize update ----------------
template <bool DEC>
__global__ void fin_upd(const float* __restrict__ bias, const float* __restrict__ projW,
                        const float* __restrict__ projb, float* __restrict__ out, int t) {
    int tid = threadIdx.x;
    int row = blockIdx.x * 8 + (tid >> 5);
    int j = tid & 31;
    float hc0 = tanhf(g_uP1[row * HH + j] + g_uP2[row * HH + j] + bias[j]);
    float hc1 = tanhf(g_uP1[row * HH + j + 32] + g_uP2[row * HH + j + 32] + bias[j + 32]);
    float r0 = g_r[row * HH + j], r1 = g_r[row * HH + j + 32];
    float h0 = g_h[row * HH + j], h1 = g_h[row * HH + j + 32];
    float hn0 = r0 * h0 + (1.f - r0) * hc0;
    float hn1 = r1 * h1 + (1.f - r1) * hc1;
    g_h[row * HH + j] = hn0;
    g_h[row * HH + j + 32] = hn1;
    if (DEC) {
        float p = hn0 * projW[j] + hn1 * projW[j + 32];
#pragma unroll
        for (int o = 16; o; o >>= 1) p += __shfl_xor_sync(0xffffffffu, p, o);
        if (j == 0) {
            float go = p + projb[0];
            g_go[row] = go;
            int b = row >> 9, n = row & (NN - 1);
            out[(b * TSTEPS + t) * NN + n] = go;
        }
    }
}

#define SMEMB 78848

// ---------------- launch ----------------
extern "C" void kernel_launch(void* const* d_in, const int* in_sizes, int n_in,
                              void* d_out, int out_size) {
    const float* x    = (const float*)d_in[0];
    const float* ycov = (const float*)d_in[1];
    const float* ne   = (const float*)d_in[2];
    const float* egW  = (const float*)d_in[3];
    const float* egb  = (const float*)d_in[4];
    const float* euW  = (const float*)d_in[5];
    const float* eub  = (const float*)d_in[6];
    const float* dgW  = (const float*)d_in[7];
    const float* dgb  = (const float*)d_in[8];
    const float* duW  = (const float*)d_in[9];
    const float* dub  = (const float*)d_in[10];
    const float* pW   = (const float*)d_in[11];
    const float* pb   = (const float*)d_in[12];
    const float* hW   = (const float*)d_in[13];
    const float* hb   = (const float*)d_in[14];
    float* out = (float*)d_out;

    cudaFuncSetAttribute(conv_fused<false, 1, 0, 128>, cudaFuncAttributeMaxDynamicSharedMemorySize, SMEMB);
    cudaFuncSetAttribute(conv_fused<false, 1, 0, 64>,  cudaFuncAttributeMaxDynamicSharedMemorySize, SMEMB);
    cudaFuncSetAttribute(conv_fused<true, 2, 1, 128>,  cudaFuncAttributeMaxDynamicSharedMemorySize, SMEMB);
    cudaFuncSetAttribute(conv_fused<true, 2, 1, 64>,   cudaFuncAttributeMaxDynamicSharedMemorySize, SMEMB);

    zero_state<<<(BATCH * NN * HH + 255) / 256, 256>>>();
    graph_build<false><<<NN, 256>>>(ne);
    gemm512<0, false><<<dim3(8, 8, 1), 128>>>(0, 0);
    gemm512<1, false><<<dim3(8, 8, 1), 128>>>(0, 1);
    gemm512<2, false><<<dim3(8, 8, 1), 128>>>(1, 0);

    // weight repacks: famA = W[0 .. 2*CIN), famB = W[2*CIN .. 3*CIN)
    {
        float *p;
        cudaGetSymbolAddress((void**)&p, g_WgAh);
        float *wgAh = p, *wgAh1 = p + 160 * 128;
        cudaGetSymbolAddress((void**)&p, g_WgAl);
        float *wgAl = p, *wgAl1 = p + 160 * 128;
        cudaGetSymbolAddress((void**)&p, g_WgBh);
        float *wgBh = p, *wgBh1 = p + 96 * 128;
        cudaGetSymbolAddress((void**)&p, g_WgBl);
        float *wgBl = p, *wgBl1 = p + 96 * 128;
        cudaGetSymbolAddress((void**)&p, g_WuAh);
        float *wuAh = p, *wuAh1 = p + 160 * 64;
        cudaGetSymbolAddress((void**)&p, g_WuAl);
        float *wuAl = p, *wuAl1 = p + 160 * 64;
        cudaGetSymbolAddress((void**)&p, g_WuBh);
        float *wuBh = p, *wuBh1 = p + 96 * 64;
        cudaGetSymbolAddress((void**)&p, g_WuBl);
        float *wuBl = p, *wuBl1 = p + 96 * 64;
        repack_w<<<(160 * 128 + 255) / 256, 256>>>(egW, wgAh, wgAl, 0, 130, 128, 160);
        repack_w<<<(96 * 128 + 255) / 256, 256>>>(egW, wgBh, wgBl, 130, 65, 128, 96);
        repack_w<<<(160 * 64 + 255) / 256, 256>>>(euW, wuAh, wuAl, 0, 130, 64, 160);
        repack_w<<<(96 * 64 + 255) / 256, 256>>>(euW, wuBh, wuBl, 130, 65, 64, 96);
        repack_w<<<(160 * 128 + 255) / 256, 256>>>(dgW, wgAh1, wgAl1, 0, 132, 128, 160);
        repack_w<<<(96 * 128 + 255) / 256, 256>>>(dgW, wgBh1, wgBl1, 132, 66, 128, 96);
        repack_w<<<(160 * 64 + 255) / 256, 256>>>(duW, wuAh1, wuAl1, 0, 132, 64, 160);
        repack_w<<<(96 * 64 + 255) / 256, 256>>>(duW, wuBh1, wuBl1, 132, 66, 64, 96);
    }

    dim3 cg(16, BATCH);
    // encoder
    for (int t = 0; t < TSTEPS; t++) {
        conv_fused<false, 1, 0, 128><<<cg, 128, SMEMB>>>(0, x, t);
        fin_gate<<<BATCH * NN / 4, 256>>>(egb);
        conv_fused<false, 1, 0, 64><<<cg, 128, SMEMB>>>(0, x, t);
        fin_upd<false><<<BATCH * NN / 8, 256>>>(eub, nullptr, nullptr, nullptr, 0);
    }
    // dynamic graph + A2d
    hyper_kernel<<<BATCH * NN / 16, 256>>>(ne, hW, hb);
    graph_build<true><<<BATCH * NN, 256>>>(nullptr);
    gemm512<0, true><<<dim3(8, 8, BATCH), 128>>>(0, 0);
    gemm512<1, true><<<dim3(8, 8, BATCH), 128>>>(0, 1);
    gemm512<2, true><<<dim3(8, 8, BATCH), 128>>>(1, 0);
    // decoder
    for (int t = 0; t < TSTEPS; t++) {
        conv_fused<true, 2, 1, 128><<<cg, 128, SMEMB>>>(1, ycov, t);
        fin_gate<<<BATCH * NN / 4, 256>>>(dgb);
        conv_fused<true, 2, 1, 64><<<cg, 128, SMEMB>>>(1, ycov, t);
        fin_upd<true><<<BATCH * NN / 8, 256>>>(dub, pW, pb, out, t);
    }
}

// round 10
// speedup vs baseline: 1.0856x; 1.0856x over previous
#include <cuda_runtime.h>
#include <math.h>
#include <stdint.h>

#define BATCH 32
#define TSTEPS 12
#define NN 512
#define HH 64
#define EE 10

// ---------------- device state ----------------
__device__ float g_A[NN * NN];
__device__ float g_Alo[NN * NN];
__device__ float g_A2s[NN * NN];
__device__ float g_Ad[BATCH * NN * NN];
__device__ float g_Adlo[BATCH * NN * NN];
__device__ float g_A2d[BATCH * NN * NN];
__device__ float g_h[BATCH * NN * HH];
__device__ float g_zh[BATCH * NN * HH];
__device__ float g_r[BATCH * NN * HH];
__device__ float g_u1m[BATCH * NN * HH];
__device__ float g_u2m[BATCH * NN * HH];
__device__ float g_y1[BATCH * NN * 2];
__device__ float g_y2[BATCH * NN * 2];
__device__ float g_Edyn[BATCH * NN * EE];
__device__ float g_go[BATCH * NN];

__device__ __forceinline__ uint32_t tf32cvt(float x) {
    uint32_t r;
    asm("cvt.rna.tf32.f32 %0, %1;" : "=r"(r) : "f"(x));
    return r;
}

__device__ __forceinline__ void mma_tf32(float* d, uint32_t a0, uint32_t a1, uint32_t a2,
                                         uint32_t a3, uint32_t b0, uint32_t b1) {
    asm volatile(
        "mma.sync.aligned.m16n8k8.row.col.f32.tf32.tf32.f32 "
        "{%0,%1,%2,%3},{%4,%5,%6,%7},{%8,%9},{%0,%1,%2,%3};"
        : "+f"(d[0]), "+f"(d[1]), "+f"(d[2]), "+f"(d[3])
        : "r"(a0), "r"(a1), "r"(a2), "r"(a3), "r"(b0), "r"(b1));
}

__device__ __forceinline__ void cp_async16(uint32_t smem, const void* gmem) {
    asm volatile("cp.async.cg.shared.global [%0], [%1], 16;" :: "r"(smem), "l"(gmem));
}
__device__ __forceinline__ void cp_commit() { asm volatile("cp.async.commit_group;"); }
__device__ __forceinline__ void cp_wait0() { asm volatile("cp.async.wait_group 0;"); }

// ---------------- init ----------------
__global__ void zero_state() {
    int i = blockIdx.x * 256 + threadIdx.x;
    if (i < BATCH * NN * HH) g_h[i] = 0.f;
    if (i < BATCH * NN) g_go[i] = 0.f;
}

// ---------------- graph build (hi/lo) ----------------
template <bool DYN>
__global__ void graph_build(const float* __restrict__ emb) {
    __shared__ float Es[NN * EE];
    __shared__ float red[8];
    int blk = blockIdx.x;
    int b = DYN ? (blk >> 9) : 0;
    int row = blk & (NN - 1);
    const float* E = DYN ? (g_Edyn + b * NN * EE) : emb;
    int tid = threadIdx.x;
    for (int i = tid; i < NN * EE; i += 256) Es[i] = E[i];
    __syncthreads();
    float er[EE];
#pragma unroll
    for (int j = 0; j < EE; j++) er[j] = Es[row * EE + j];
    float v0 = 0.f, v1 = 0.f;
    int c0 = tid, c1 = tid + 256;
#pragma unroll
    for (int j = 0; j < EE; j++) {
        v0 += er[j] * Es[c0 * EE + j];
        v1 += er[j] * Es[c1 * EE + j];
    }
    v0 = fmaxf(v0, 0.f);
    v1 = fmaxf(v1, 0.f);
    float m = fmaxf(v0, v1);
#pragma unroll
    for (int o = 16; o; o >>= 1) m = fmaxf(m, __shfl_xor_sync(0xffffffffu, m, o));
    if ((tid & 31) == 0) red[tid >> 5] = m;
    __syncthreads();
    m = red[0];
#pragma unroll
    for (int i = 1; i < 8; i++) m = fmaxf(m, red[i]);
    float e0 = expf(v0 - m), e1 = expf(v1 - m);
    float s = e0 + e1;
#pragma unroll
    for (int o = 16; o; o >>= 1) s += __shfl_xor_sync(0xffffffffu, s, o);
    __syncthreads();
    if ((tid & 31) == 0) red[tid >> 5] = s;
    __syncthreads();
    float tot = 0.f;
#pragma unroll
    for (int i = 0; i < 8; i++) tot += red[i];
    float inv = 1.f / tot;
    size_t off = DYN ? ((size_t)b * NN * NN + (size_t)row * NN) : ((size_t)row * NN);
    float* hi = (DYN ? g_Ad : g_A) + off;
    float* lo = (DYN ? g_Adlo : g_Alo) + off;
    float a0 = e0 * inv, a1 = e1 * inv;
    float h0 = __uint_as_float(tf32cvt(a0));
    float h1 = __uint_as_float(tf32cvt(a1));
    hi[c0] = h0; hi[c1] = h1;
    lo[c0] = __uint_as_float(tf32cvt(a0 - h0));
    lo[c1] = __uint_as_float(tf32cvt(a1 - h1));
}

// ---------------- hypernetwork ----------------
__global__ void hyper_kernel(const float* __restrict__ ne,
                             const float* __restrict__ hW,
                             const float* __restrict__ hb) {
    __shared__ float Ws[HH * EE];
    int tid = threadIdx.x;
    for (int i = tid; i < HH * EE; i += 256) Ws[i] = hW[i];
    __syncthreads();
    int lr = tid >> 4, e = tid & 15;
    int row = blockIdx.x * 16 + lr;
    if (e < EE) {
        float acc = hb[e];
        const float* hp = g_h + row * HH;
#pragma unroll
        for (int j = 0; j < HH; j++) acc += hp[j] * Ws[j * EE + e];
        int n = row & (NN - 1);
        g_Edyn[row * EE + e] = ne[n * EE + e] + acc;
    }
}

// ---------------- gemm512f: fused A2 = tf32(2*(Ah@Bh + Ah@Bl + Al@Bh)) ----------------
#define AS 36
#define XS 72
// dynamic smem: 2 bufs x (Ah,Al,Bh,Bl) x 2304 floats = 73728 B
#define SMEMF 73728
template <bool DYN>
__global__ void __launch_bounds__(128) gemm512f() {
    extern __shared__ float sm[];
    int i0 = blockIdx.x * 64;
    int j0 = blockIdx.y * 64;
    int bz = blockIdx.z;
    size_t boff = (size_t)bz * NN * NN;
    const float* Ahi = (DYN ? g_Ad : g_A) + boff + (size_t)i0 * NN;
    const float* Alo = (DYN ? g_Adlo : g_Alo) + boff + (size_t)i0 * NN;
    const float* Bhi = (DYN ? g_Ad : g_A) + boff + j0;
    const float* Blo = (DYN ? g_Adlo : g_Alo) + boff + j0;
    float* Out = (DYN ? g_A2d : g_A2s) + boff;
    int tid = threadIdx.x;

    // buf layout (floats): Ah=+0, Al=+2304, Bh=+4608, Bl=+6912; buf stride 9216
    auto stage = [&](int buf, int k0) {
        float* base = sm + buf * 9216;
#pragma unroll
        for (int q = 0; q < 4; q++) {
            int idx = tid + q * 128;
            int r = idx >> 3, c4 = idx & 7;
            cp_async16((uint32_t)__cvta_generic_to_shared(&base[r * AS + c4 * 4]),
                       &Ahi[(size_t)r * NN + k0 + c4 * 4]);
            cp_async16((uint32_t)__cvta_generic_to_shared(&base[2304 + r * AS + c4 * 4]),
                       &Alo[(size_t)r * NN + k0 + c4 * 4]);
        }
#pragma unroll
        for (int q = 0; q < 4; q++) {
            int idx = tid + q * 128;
            int k = idx >> 4, n4 = idx & 15;
            cp_async16((uint32_t)__cvta_generic_to_shared(&base[4608 + k * XS + n4 * 4]),
                       &Bhi[(size_t)(k0 + k) * NN + n4 * 4]);
            cp_async16((uint32_t)__cvta_generic_to_shared(&base[6912 + k * XS + n4 * 4]),
                       &Blo[(size_t)(k0 + k) * NN + n4 * 4]);
        }
        cp_commit();
    };

    stage(0, 0);
    cp_wait0();
    __syncthreads();

    int lane = tid & 31, w = tid >> 5;
    int gid = lane >> 2, tq = lane & 3;
    int R = (w & 1) * 32;
    int CH = (w >> 1) * 32;
    float acc[2][4][4];
#pragma unroll
    for (int rr = 0; rr < 2; rr++)
#pragma unroll
        for (int j = 0; j < 4; j++)
#pragma unroll
            for (int c = 0; c < 4; c++) acc[rr][j][c] = 0.f;

    for (int it = 0; it < 16; it++) {
        int buf = it & 1, nxt = buf ^ 1;
        if (it < 15) stage(nxt, (it + 1) * 32);
        const float* Ah = sm + buf * 9216;
        const float* Al = Ah + 2304;
        const float* Bh = Ah + 4608;
        const float* Bl = Ah + 6912;
#pragma unroll
        for (int ks = 0; ks < 4; ks++) {
            int kb = ks * 8;
            uint32_t bh0[4], bh1[4], bl0[4], bl1[4];
#pragma unroll
            for (int j = 0; j < 4; j++) {
                int nb = CH + j * 8;
                bh0[j] = __float_as_uint(Bh[(kb + tq) * XS + nb + gid]);
                bh1[j] = __float_as_uint(Bh[(kb + tq + 4) * XS + nb + gid]);
                bl0[j] = __float_as_uint(Bl[(kb + tq) * XS + nb + gid]);
                bl1[j] = __float_as_uint(Bl[(kb + tq + 4) * XS + nb + gid]);
            }
#pragma unroll
            for (int rr = 0; rr < 2; rr++) {
                int Rr = R + rr * 16;
                uint32_t ah0 = __float_as_uint(Ah[(Rr + gid) * AS + kb + tq]);
                uint32_t ah1 = __float_as_uint(Ah[(Rr + gid + 8) * AS + kb + tq]);
                uint32_t ah2 = __float_as_uint(Ah[(Rr + gid) * AS + kb + tq + 4]);
                uint32_t ah3 = __float_as_uint(Ah[(Rr + gid + 8) * AS + kb + tq + 4]);
                uint32_t al0 = __float_as_uint(Al[(Rr + gid) * AS + kb + tq]);
                uint32_t al1 = __float_as_uint(Al[(Rr + gid + 8) * AS + kb + tq]);
                uint32_t al2 = __float_as_uint(Al[(Rr + gid) * AS + kb + tq + 4]);
                uint32_t al3 = __float_as_uint(Al[(Rr + gid + 8) * AS + kb + tq + 4]);
#pragma unroll
                for (int j = 0; j < 4; j++) {
                    mma_tf32(acc[rr][j], ah0, ah1, ah2, ah3, bh0[j], bh1[j]);
                    mma_tf32(acc[rr][j], ah0, ah1, ah2, ah3, bl0[j], bl1[j]);
                    mma_tf32(acc[rr][j], al0, al1, al2, al3, bh0[j], bh1[j]);
                }
            }
        }
        if (it < 15) cp_wait0();
        __syncthreads();
    }

#pragma unroll
    for (int rr = 0; rr < 2; rr++) {
#pragma unroll
        for (int j = 0; j < 4; j++) {
            int col = j0 + CH + j * 8 + 2 * tq;
            int row0 = i0 + R + rr * 16 + gid;
            int row1 = row0 + 8;
#pragma unroll
            for (int e = 0; e < 4; e++) {
                int row = (e < 2) ? row0 : row1;
                int cc = col + (e & 1);
                Out[(size_t)row * NN + cc] = __uint_as_float(tf32cvt(2.f * acc[rr][j][e]));
            }
        }
    }
}

// ---------------- conv: u1m = A@X, u2m = 2A^2@X, leads y1/y2 (validated R7) ----------------
// grid (16, BATCH), 128 threads. blockIdx.x 0-7: A family, 8-15: 2A^2 family. Full K.
template <bool BA, int L, int LMODE>
__global__ void __launch_bounds__(128) conv_mma(int xsel, const float* __restrict__ xsrc, int t) {
    __shared__ float As[2][64 * AS];
    __shared__ float Xs[2][32 * XS];
    __shared__ float xsl[L > 0 ? NN * L : 1];
    int b = blockIdx.y;
    int rt = blockIdx.x;
    bool second = rt >= 8;
    int i0 = (second ? rt - 8 : rt) * 64;
    const float* Mbase;
    if (BA) Mbase = (second ? g_A2d : g_Ad) + (size_t)b * NN * NN;
    else    Mbase = second ? g_A2s : g_A;
    Mbase += (size_t)i0 * NN;
    const float* Xb = (xsel ? g_zh : g_h) + b * NN * HH;
    float* Ob = (second ? g_u2m : g_u1m) + b * NN * HH;
    int tid = threadIdx.x;

    if (L > 0) {
        for (int i = tid; i < NN * L; i += 128) {
            int k = i / L, c = i - (i / L) * L;
            float v;
            if (LMODE == 0) v = xsrc[(b * TSTEPS + t) * NN + k];
            else v = (c == 0) ? g_go[b * NN + k] : xsrc[(b * TSTEPS + t) * NN + k];
            xsl[i] = v;
        }
    }

    float4 xr[4];
#pragma unroll
    for (int q = 0; q < 4; q++) {
        int idx = tid + q * 128;
        int r = idx >> 3, c4 = idx & 7;
        cp_async16((uint32_t)__cvta_generic_to_shared(&As[0][r * AS + c4 * 4]),
                   &Mbase[(size_t)r * NN + c4 * 4]);
    }
    cp_commit();
#pragma unroll
    for (int q = 0; q < 4; q++) {
        int idx = tid + q * 128;
        int k = idx >> 4, n4 = idx & 15;
        xr[q] = *(const float4*)&Xb[k * HH + n4 * 4];
    }
#pragma unroll
    for (int q = 0; q < 4; q++) {
        int idx = tid + q * 128;
        int k = idx >> 4, n4 = idx & 15;
        float4 v = xr[q];
        v.x = __uint_as_float(tf32cvt(v.x));
        v.y = __uint_as_float(tf32cvt(v.y));
        v.z = __uint_as_float(tf32cvt(v.z));
        v.w = __uint_as_float(tf32cvt(v.w));
        *(float4*)&Xs[0][k * XS + n4 * 4] = v;
    }
    cp_wait0();
    __syncthreads();

    int lane = tid & 31, w = tid >> 5;
    int gid = lane >> 2, tq = lane & 3;
    int R = (w & 1) * 32;
    int CH = (w >> 1) * 32;
    float acc[2][4][4];
#pragma unroll
    for (int rr = 0; rr < 2; rr++)
#pragma unroll
        for (int j = 0; j < 4; j++)
#pragma unroll
            for (int c = 0; c < 4; c++) acc[rr][j][c] = 0.f;

    int lrow = tid >> 1, lhalf = tid & 1;
    float lacc0 = 0.f, lacc1 = 0.f;

    for (int it = 0; it < 16; it++) {
        int buf = it & 1, nxt = buf ^ 1;
        int k0n = (it + 1) * 32;
        if (it < 15) {
#pragma unroll
            for (int q = 0; q < 4; q++) {
                int idx = tid + q * 128;
                int r = idx >> 3, c4 = idx & 7;
                cp_async16((uint32_t)__cvta_generic_to_shared(&As[nxt][r * AS + c4 * 4]),
                           &Mbase[(size_t)r * NN + k0n + c4 * 4]);
            }
            cp_commit();
#pragma unroll
            for (int q = 0; q < 4; q++) {
                int idx = tid + q * 128;
                int k = idx >> 4, n4 = idx & 15;
                xr[q] = *(const float4*)&Xb[(k0n + k) * HH + n4 * 4];
            }
        }
        const float* Ac = As[buf];
        const float* Xc = Xs[buf];
#pragma unroll
        for (int kss = 0; kss < 4; kss++) {
            int kb = kss * 8;
            uint32_t b0[4], b1[4];
#pragma unroll
            for (int j = 0; j < 4; j++) {
                int nb = CH + j * 8;
                b0[j] = __float_as_uint(Xc[(kb + tq) * XS + nb + gid]);
                b1[j] = __float_as_uint(Xc[(kb + tq + 4) * XS + nb + gid]);
            }
#pragma unroll
            for (int rr = 0; rr < 2; rr++) {
                int Rr = R + rr * 16;
                uint32_t a0 = __float_as_uint(Ac[(Rr + gid) * AS + kb + tq]);
                uint32_t a1 = __float_as_uint(Ac[(Rr + gid + 8) * AS + kb + tq]);
                uint32_t a2 = __float_as_uint(Ac[(Rr + gid) * AS + kb + tq + 4]);
                uint32_t a3 = __float_as_uint(Ac[(Rr + gid + 8) * AS + kb + tq + 4]);
#pragma unroll
                for (int j = 0; j < 4; j++)
                    mma_tf32(acc[rr][j], a0, a1, a2, a3, b0[j], b1[j]);
            }
        }
        if (L > 0) {
            int k0 = it * 32;
#pragma unroll
            for (int j = 0; j < 16; j++) {
                int k = lhalf * 16 + j;
                float a = Ac[lrow * AS + k];
                lacc0 += a * xsl[(k0 + k) * L];
                if (L == 2) lacc1 += a * xsl[(k0 + k) * L + 1];
            }
        }
        if (it < 15) {
#pragma unroll
            for (int q = 0; q < 4; q++) {
                int idx = tid + q * 128;
                int k = idx >> 4, n4 = idx & 15;
                float4 v = xr[q];
                v.x = __uint_as_float(tf32cvt(v.x));
                v.y = __uint_as_float(tf32cvt(v.y));
                v.z = __uint_as_float(tf32cvt(v.z));
                v.w = __uint_as_float(tf32cvt(v.w));
                *(float4*)&Xs[nxt][k * XS + n4 * 4] = v;
            }
            cp_wait0();
        }
        __syncthreads();
    }

    if (L > 0) {
        lacc0 += __shfl_xor_sync(0xffffffffu, lacc0, 1);
        if (L == 2) lacc1 += __shfl_xor_sync(0xffffffffu, lacc1, 1);
        if (lhalf == 0) {
            float* dst = second ? g_y2 : g_y1;
            float sc = second ? 0.5f : 1.f;
            dst[(b * NN + i0 + lrow) * L] = sc * lacc0;
            if (L == 2) dst[(b * NN + i0 + lrow) * L + 1] = sc * lacc1;
        }
    }

#pragma unroll
    for (int rr = 0; rr < 2; rr++) {
#pragma unroll
        for (int j = 0; j < 4; j++) {
            int col = CH + j * 8 + 2 * tq;
            int row0 = i0 + R + rr * 16 + gid;
            int row1 = row0 + 8;
            int o0 = row0 * HH + col;
            int o1 = row1 * HH + col;
            *(float2*)&Ob[o0] = make_float2(acc[rr][j][0], acc[rr][j][1]);
            *(float2*)&Ob[o1] = make_float2(acc[rr][j][2], acc[rr][j][3]);
        }
    }
}

// ---------------- Xs assembly helper (validated R7 semantics) ----------------
// seg1 = u1m (raw = A@main); seg2 = u2m_raw - main (= (2A^2-I)@main)
template <int CIN, bool ENC, bool UPD, int NT>
__device__ __forceinline__ void load_xs(float* Xs, int r0, const float* __restrict__ xsrc, int t) {
    constexpr int K = 3 * CIN;
    constexpr int L = CIN - HH;
    int tid = threadIdx.x;
    for (int i = tid; i < 32 * K; i += NT) {
        int r = i / K, k = i - r * K;
        int seg = k / CIN, c = k - seg * CIN;
        int row = r0 + r, b = row >> 9, n = row & (NN - 1);
        float v;
        if (c < L) {
            float x0;
            if (ENC) x0 = xsrc[(b * TSTEPS + t) * NN + n];
            else x0 = (c == 0) ? g_go[row] : xsrc[(b * TSTEPS + t) * NN + n];
            if (seg == 0) v = x0;
            else if (seg == 1) v = g_y1[row * L + c];
            else v = 2.f * g_y2[row * L + c] - x0;
        } else {
            int cm = c - L;
            float mainv = (UPD ? g_zh : g_h)[row * HH + cm];
            if (seg == 0) v = mainv;
            else if (seg == 1) v = g_u1m[row * HH + cm];
            else v = g_u2m[row * HH + cm] - mainv;
        }
        Xs[i] = v;
    }
}

// ---------------- gate: zr = sigmoid(X @ W + b); zh = z*h; r saved ----------------
// 32 rows/block, 128 threads: each thread 8 rows x 4 cols (tc, tc+32, tc+64, tc+96)
template <int CIN, bool ENC>
__global__ void __launch_bounds__(128) gate_kernel(const float* __restrict__ W,
                                                   const float* __restrict__ bias,
                                                   const float* __restrict__ xsrc, int t) {
    constexpr int K = 3 * CIN;
    __shared__ float Xs[32 * K];
    __shared__ float Ws[32 * 128];
    int r0 = blockIdx.x * 32;
    int tid = threadIdx.x;
    load_xs<CIN, ENC, false, 128>(Xs, r0, xsrc, t);
    int tc = tid & 31, tr = tid >> 5;
    float acc[8][4];
#pragma unroll
    for (int i = 0; i < 8; i++)
#pragma unroll
        for (int j = 0; j < 4; j++) acc[i][j] = 0.f;
    for (int k0 = 0; k0 < K; k0 += 32) {
        int kt = min(32, K - k0);
        __syncthreads();
        for (int l = tid; l < kt * 128; l += 128) Ws[l] = W[k0 * 128 + l];
        __syncthreads();
        if (kt == 32) {
#pragma unroll 4
            for (int kk = 0; kk < 32; kk++) {
                float w0 = Ws[kk * 128 + tc];
                float w1 = Ws[kk * 128 + tc + 32];
                float w2 = Ws[kk * 128 + tc + 64];
                float w3 = Ws[kk * 128 + tc + 96];
#pragma unroll
                for (int i = 0; i < 8; i++) {
                    float xv = Xs[(tr + 4 * i) * K + k0 + kk];
                    acc[i][0] += xv * w0;
                    acc[i][1] += xv * w1;
                    acc[i][2] += xv * w2;
                    acc[i][3] += xv * w3;
                }
            }
        } else {
            for (int kk = 0; kk < kt; kk++) {
                float w0 = Ws[kk * 128 + tc];
                float w1 = Ws[kk * 128 + tc + 32];
                float w2 = Ws[kk * 128 + tc + 64];
                float w3 = Ws[kk * 128 + tc + 96];
#pragma unroll
                for (int i = 0; i < 8; i++) {
                    float xv = Xs[(tr + 4 * i) * K + k0 + kk];
                    acc[i][0] += xv * w0;
                    acc[i][1] += xv * w1;
                    acc[i][2] += xv * w2;
                    acc[i][3] += xv * w3;
                }
            }
        }
    }
    float b0 = bias[tc], b1 = bias[tc + 32], b2 = bias[tc + 64], b3 = bias[tc + 96];
#pragma unroll
    for (int i = 0; i < 8; i++) {
        int row = r0 + tr + 4 * i;
        float z0 = 1.f / (1.f + expf(-(acc[i][0] + b0)));
        float z1 = 1.f / (1.f + expf(-(acc[i][1] + b1)));
        float rr0 = 1.f / (1.f + expf(-(acc[i][2] + b2)));
        float rr1 = 1.f / (1.f + expf(-(acc[i][3] + b3)));
        g_zh[row * HH + tc] = z0 * g_h[row * HH + tc];
        g_zh[row * HH + tc + 32] = z1 * g_h[row * HH + tc + 32];
        g_r[row * HH + tc] = rr0;
        g_r[row * HH + tc + 32] = rr1;
    }
}

// ---------------- update: hc = tanh(X@W+b); h = r*h+(1-r)*hc; (dec) go = h@pW+pb ----------------
// 32 rows/block, 128 threads: each thread 4 rows x 4 cols (tc, tc+16, tc+32, tc+48), tc in [0,16)
template <int CIN, bool DEC>
__global__ void __launch_bounds__(128) upd_kernel(const float* __restrict__ W,
                                                  const float* __restrict__ bias,
                                                  const float* __restrict__ projW,
                                                  const float* __restrict__ projb,
                                                  float* __restrict__ out,
                                                  const float* __restrict__ xsrc, int t) {
    constexpr int K = 3 * CIN;
    __shared__ float Xs[32 * K];
    __shared__ float Ws[32 * 64];
    int r0 = blockIdx.x * 32;
    int tid = threadIdx.x;
    load_xs<CIN, !DEC, true, 128>(Xs, r0, xsrc, t);
    int tc = tid & 15, tr = tid >> 4;  // tr 0..7
    float acc[4][4];
#pragma unroll
    for (int i = 0; i < 4; i++)
#pragma unroll
        for (int j = 0; j < 4; j++) acc[i][j] = 0.f;
    for (int k0 = 0; k0 < K; k0 += 32) {
        int kt = min(32, K - k0);
        __syncthreads();
        for (int l = tid; l < kt * 64; l += 128) Ws[l] = W[k0 * 64 + l];
        __syncthreads();
        if (kt == 32) {
#pragma unroll 4
            for (int kk = 0; kk < 32; kk++) {
                float w0 = Ws[kk * 64 + tc];
                float w1 = Ws[kk * 64 + tc + 16];
                float w2 = Ws[kk * 64 + tc + 32];
                float w3 = Ws[kk * 64 + tc + 48];
#pragma unroll
                for (int i = 0; i < 4; i++) {
                    float xv = Xs[(tr + 8 * i) * K + k0 + kk];
                    acc[i][0] += xv * w0;
                    acc[i][1] += xv * w1;
                    acc[i][2] += xv * w2;
                    acc[i][3] += xv * w3;
                }
            }
        } else {
            for (int kk = 0; kk < kt; kk++) {
                float w0 = Ws[kk * 64 + tc];
                float w1 = Ws[kk * 64 + tc + 16];
                float w2 = Ws[kk * 64 + tc + 32];
                float w3 = Ws[kk * 64 + tc + 48];
#pragma unroll
                for (int i = 0; i < 4; i++) {
                    float xv = Xs[(tr + 8 * i) * K + k0 + kk];
                    acc[i][0] += xv * w0;
                    acc[i][1] += xv * w1;
                    acc[i][2] += xv * w2;
                    acc[i][3] += xv * w3;
                }
            }
        }
    }
    float bb[4], pw[4];
#pragma unroll
    for (int j = 0; j < 4; j++) {
        bb[j] = bias[tc + 16 * j];
        pw[j] = DEC ? projW[tc + 16 * j] : 0.f;
    }
#pragma unroll
    for (int i = 0; i < 4; i++) {
        int row = r0 + tr + 8 * i;
        float p = 0.f;
#pragma unroll
        for (int j = 0; j < 4; j++) {
            int col = tc + 16 * j;
            float hc = tanhf(acc[i][j] + bb[j]);
            float rr = g_r[row * HH + col];
            float h0 = g_h[row * HH + col];
            float hn = rr * h0 + (1.f - rr) * hc;
            g_h[row * HH + col] = hn;
            if (DEC) p += hn * pw[j];
        }
        if (DEC) {
            // reduce within 16-lane group (lanes with same tr in this warp)
            p += __shfl_xor_sync(0xffffffffu, p, 8);
            p += __shfl_xor_sync(0xffffffffu, p, 4);
            p += __shfl_xor_sync(0xffffffffu, p, 2);
            p += __shfl_xor_sync(0xffffffffu, p, 1);
            if (tc == 0) {
                float go = p + projb[0];
                g_go[row] = go;
                int b = row >> 9, n = row & (NN - 1);
                out[(b * TSTEPS + t) * NN + n] = go;
            }
        }
    }
}

// ---------------- launch ----------------
extern "C" void kernel_launch(void* const* d_in, const int* in_sizes, int n_in,
                              void* d_out, int out_size) {
    const float* x    = (const float*)d_in[0];
    const float* ycov = (const float*)d_in[1];
    const float* ne   = (const float*)d_in[2];
    const float* egW  = (const float*)d_in[3];
    const float* egb  = (const float*)d_in[4];
    const float* euW  = (const float*)d_in[5];
    const float* eub  = (const float*)d_in[6];
    const float* dgW  = (const float*)d_in[7];
    const float* dgb  = (const float*)d_in[8];
    const float* duW  = (const float*)d_in[9];
    const float* dub  = (const float*)d_in[10];
    const float* pW   = (const float*)d_in[11];
    const float* pb   = (const float*)d_in[12];
    const float* hW   = (const float*)d_in[13];
    const float* hb   = (const float*)d_in[14];
    float* out = (float*)d_out;

    cudaFuncSetAttribute(gemm512f<false>, cudaFuncAttributeMaxDynamicSharedMemorySize, SMEMF);
    cudaFuncSetAttribute(gemm512f<true>,  cudaFuncAttributeMaxDynamicSharedMemorySize, SMEMF);

    zero_state<<<(BATCH * NN * HH + 255) / 256, 256>>>();
    graph_build<false><<<NN, 256>>>(ne);
    gemm512f<false><<<dim3(8, 8, 1), 128, SMEMF>>>();

    dim3 cg(16, BATCH);
    // encoder
    for (int t = 0; t < TSTEPS; t++) {
        conv_mma<false, 1, 0><<<cg, 128>>>(0, x, t);   // u1=A@h, u2=2A^2@h, y1, y2
        gate_kernel<65, true><<<BATCH * NN / 32, 128>>>(egW, egb, x, t);
        conv_mma<false, 0, 0><<<cg, 128>>>(1, nullptr, 0);  // u1=A@zh, u2=2A^2@zh
        upd_kernel<65, false><<<BATCH * NN / 32, 128>>>(euW, eub, nullptr, nullptr, nullptr, x, t);
    }
    // dynamic graph + A2d
    hyper_kernel<<<BATCH * NN / 16, 256>>>(ne, hW, hb);
    graph_build<true><<<BATCH * NN, 256>>>(nullptr);
    gemm512f<true><<<dim3(8, 8, BATCH), 128, SMEMF>>>();
    // decoder
    for (int t = 0; t < TSTEPS; t++) {
        conv_mma<true, 2, 1><<<cg, 128>>>(0, ycov, t);
        gate_kernel<66, false><<<BATCH * NN / 32, 128>>>(dgW, dgb, ycov, t);
        conv_mma<true, 0, 0><<<cg, 128>>>(1, nullptr, 0);
        upd_kernel<66, true><<<BATCH * NN / 32, 128>>>(duW, dub, pW, pb, out, ycov, t);
    }
}